// round 12
// baseline (speedup 1.0000x reference)
#include <cuda_runtime.h>
#include <math.h>

#define CCH   256
#define HW    384
#define NPIX  (HW*HW)        // 147456 elems per channel
#define NQ    (NPIX/4)       // 36864 float4 per channel
#define QPR   (HW/4)         // 96 float4 per row
#define NPART 36             // bulk-sum partials per (input, channel): 36*1024 = NQ
#define INVN  (1.0f/(382.0f*382.0f))

// All scratch slots are written every launch (no init kernel needed).
__device__ float g_part[2][CCH][NPART];  // bulk-sum partials
__device__ float g_row [2][CCH][4];      // row sums, rows {0,1,382,383}
__device__ float g_col [2][CCH][4];      // col sums, cols {0,1,382,383}
__device__ float g_corn[2][CCH][16];     // [row class][col class]
__device__ float g_cf  [2][CCH];         // final combine coefficients

// ---------------------------------------------------------------------------
// Kernel 1a: pure bulk sum, combine-shaped. grid = (NPART, 2, CCH), block 256.
// 4 independent front-batched float4 loads per thread, FADD tree, warp
// shuffle, single partial store. Zero predicates in the hot path.
// ---------------------------------------------------------------------------
__global__ void __launch_bounds__(256) sum_kernel(const float* __restrict__ in1,
                                                  const float* __restrict__ in2) {
    const int b     = blockIdx.x;
    const int which = blockIdx.y;
    const int c     = blockIdx.z;
    const float4* p = ((const float4*)(which ? in2 : in1))
                      + (size_t)c * NQ + (size_t)b * 1024 + threadIdx.x;

    float4 v0 = __ldcs(p);
    float4 v1 = __ldcs(p + 256);
    float4 v2 = __ldcs(p + 512);
    float4 v3 = __ldcs(p + 768);

    float s = ((v0.x + v0.y) + (v0.z + v0.w))
            + ((v1.x + v1.y) + (v1.z + v1.w))
            + ((v2.x + v2.y) + (v2.z + v2.w))
            + ((v3.x + v3.y) + (v3.z + v3.w));

    #pragma unroll
    for (int off = 16; off > 0; off >>= 1)
        s += __shfl_down_sync(0xffffffffu, s, off);

    __shared__ float red[8];
    const int warp = threadIdx.x >> 5, lane = threadIdx.x & 31;
    if (lane == 0) red[warp] = s;
    __syncthreads();
    if (threadIdx.x == 0) {
        float T = ((red[0] + red[1]) + (red[2] + red[3]))
                + ((red[4] + red[5]) + (red[6] + red[7]));
        g_part[which][c][b] = T;
    }
}

// ---------------------------------------------------------------------------
// Kernel 1b: border stats. grid = (CCH, 2), block 128 (4 warps).
// Phase A: col sums over all 384 rows (each thread handles 3 rows) + corners.
// Phase B: warp w sums border row {0,1,382,383}[w].
// ---------------------------------------------------------------------------
__global__ void __launch_bounds__(128) border_kernel(const float* __restrict__ in1,
                                                     const float* __restrict__ in2) {
    const int c     = blockIdx.x;
    const int which = blockIdx.y;
    const float4* x = ((const float4*)(which ? in2 : in1)) + (size_t)c * NQ;

    const int tid  = threadIdx.x;
    const int warp = tid >> 5, lane = tid & 31;

    // ---- Phase A: column sums + corners ----
    float c0 = 0.0f, c1 = 0.0f, c2 = 0.0f, c3 = 0.0f;
    #pragma unroll
    for (int k = 0; k < 3; k++) {
        const int r = tid + k * 128;
        float4 a = __ldg(x + (size_t)r * QPR);            // cols 0..3
        float4 b = __ldg(x + (size_t)r * QPR + 95);       // cols 380..383
        c0 += a.x; c1 += a.y; c2 += b.z; c3 += b.w;
        if (r <= 1 || r >= 382) {
            const int rc = (r <= 1) ? r : (r - 380);      // 0..3
            g_corn[which][c][rc*4 + 0] = a.x;
            g_corn[which][c][rc*4 + 1] = a.y;
            g_corn[which][c][rc*4 + 2] = b.z;
            g_corn[which][c][rc*4 + 3] = b.w;
        }
    }
    #pragma unroll
    for (int off = 16; off > 0; off >>= 1) {
        c0 += __shfl_down_sync(0xffffffffu, c0, off);
        c1 += __shfl_down_sync(0xffffffffu, c1, off);
        c2 += __shfl_down_sync(0xffffffffu, c2, off);
        c3 += __shfl_down_sync(0xffffffffu, c3, off);
    }
    __shared__ float cw[4][4];
    if (lane == 0) { cw[warp][0] = c0; cw[warp][1] = c1; cw[warp][2] = c2; cw[warp][3] = c3; }
    __syncthreads();
    if (tid < 4)
        g_col[which][c][tid] = cw[0][tid] + cw[1][tid] + cw[2][tid] + cw[3][tid];

    // ---- Phase B: border row sums (warp w -> row RR[w]) ----
    const int RR[4] = { 0, 1, 382, 383 };
    const int R = RR[warp];
    float rs = 0.0f;
    #pragma unroll
    for (int k = 0; k < 3; k++) {
        float4 v = __ldg(x + (size_t)R * QPR + lane + k * 32);
        rs += (v.x + v.y) + (v.z + v.w);
    }
    #pragma unroll
    for (int off = 16; off > 0; off >>= 1)
        rs += __shfl_down_sync(0xffffffffu, rs, off);
    if (lane == 0) g_row[which][c][warp] = rs;
}

// ---------------------------------------------------------------------------
// Kernel 2: finalize (partials + borders -> 9 window sums per input-channel)
// fused with the per-oc matvec, sigmoid, branch flags -> coefficients.
// ---------------------------------------------------------------------------
__global__ void __launch_bounds__(256) coef_kernel(const float* __restrict__ W,
                                                   const float* __restrict__ b) {
    const int oc = blockIdx.x;
    const int ic = threadIdx.x;

    float S[2][9];
    const int ER[3][2] = { {2,3}, {0,3}, {0,1} };
    #pragma unroll
    for (int w = 0; w < 2; w++) {
        float T = 0.0f;
        #pragma unroll
        for (int k = 0; k < NPART; k++) T += g_part[w][ic][k];
        float rs0 = g_row[w][ic][0], rs1 = g_row[w][ic][1],
              rs2 = g_row[w][ic][2], rs3 = g_row[w][ic][3];
        float cs0 = g_col[w][ic][0], cs1 = g_col[w][ic][1],
              cs2 = g_col[w][ic][2], cs3 = g_col[w][ic][3];
        float Rex[3] = { rs2+rs3, rs0+rs3, rs0+rs1 };
        float Cex[3] = { cs2+cs3, cs0+cs3, cs0+cs1 };
        #pragma unroll
        for (int kh = 0; kh < 3; kh++)
            #pragma unroll
            for (int kw = 0; kw < 3; kw++) {
                float cor = 0.0f;
                #pragma unroll
                for (int i = 0; i < 2; i++)
                    #pragma unroll
                    for (int j = 0; j < 2; j++)
                        cor += g_corn[w][ic][ER[kh][i]*4 + ER[kw][j]];
                S[w][kh*3 + kw] = T - Rex[kh] - Cex[kw] + cor;
            }
    }

    const float* wrow = W + (size_t)oc * CCH * 9 + ic * 9;
    float d1 = 0.0f, d2 = 0.0f;
    #pragma unroll
    for (int k = 0; k < 9; k++) {
        float w = wrow[k];
        d1 += w * S[0][k];
        d2 += w * S[1][k];
    }
    #pragma unroll
    for (int off = 16; off > 0; off >>= 1) {
        d1 += __shfl_down_sync(0xffffffffu, d1, off);
        d2 += __shfl_down_sync(0xffffffffu, d2, off);
    }
    __shared__ float s1[8], s2[8];
    int warp = ic >> 5, lane = ic & 31;
    if (lane == 0) { s1[warp] = d1; s2[warp] = d2; }
    __syncthreads();
    if (ic == 0) {
        float D1 = 0.0f, D2 = 0.0f;
        #pragma unroll
        for (int w = 0; w < 8; w++) { D1 += s1[w]; D2 += s2[w]; }
        float bb = b[oc];
        float m1 = bb + D1 * INVN;
        float m2 = bb + D2 * INVN;
        float m3 = bb + (D1 + D2) * INVN;
        float x1 = 1.0f / (1.0f + expf(-m1));
        float x2 = 1.0f / (1.0f + expf(-m2));
        float x3 = 1.0f / (1.0f + expf(-m3));
        bool c1 = (x1 >= x2);
        bool c2 = (x1 <= x2);
        float a1 = (c1 && (x1 >= x3)) ? 1.0f : 0.0f;
        float a2 = (c2 && (x2 >= x3)) ? 1.0f : 0.0f;
        float a3 = ((c1 && (x1 < x3)) || (c2 && (x2 < x3))) ? 1.0f : 0.0f;
        g_cf[0][oc] = a1 + a3;   // multiplies input1
        g_cf[1][oc] = a2 + a3;   // multiplies input2
    }
}

// ---------------------------------------------------------------------------
// Kernel 3: out = k1[ch]*in1 + k2[ch]*in2 with load skipping (R10, proven).
// ---------------------------------------------------------------------------
__global__ void __launch_bounds__(256) combine_kernel(const float4* __restrict__ in1,
                                                      const float4* __restrict__ in2,
                                                      float4* __restrict__ out) {
    const int ch  = blockIdx.x / (NQ / 256);          // 144 blocks per channel
    const int idx = blockIdx.x * 256 + threadIdx.x;
    const float k1 = g_cf[0][ch];
    const float k2 = g_cf[1][ch];
    float4 o;
    if (k2 == 0.0f) {                 // (1,0): only input1 needed
        float4 a = __ldcs(in1 + idx);
        o.x = k1 * a.x; o.y = k1 * a.y; o.z = k1 * a.z; o.w = k1 * a.w;
    } else if (k1 == 0.0f) {          // (0,1): only input2 needed
        float4 b = __ldcs(in2 + idx);
        o.x = k2 * b.x; o.y = k2 * b.y; o.z = k2 * b.z; o.w = k2 * b.w;
    } else {                          // (1,1): both
        float4 a = __ldcs(in1 + idx);
        float4 b = __ldcs(in2 + idx);
        o.x = k1 * a.x + k2 * b.x;
        o.y = k1 * a.y + k2 * b.y;
        o.z = k1 * a.z + k2 * b.z;
        o.w = k1 * a.w + k2 * b.w;
    }
    __stcs(out + idx, o);
}

extern "C" void kernel_launch(void* const* d_in, const int* in_sizes, int n_in,
                              void* d_out, int out_size) {
    const float* in1 = (const float*)d_in[0];
    const float* in2 = (const float*)d_in[1];
    const float* W   = (const float*)d_in[2];
    const float* b   = (const float*)d_in[3];
    float* out = (float*)d_out;

    border_kernel<<<dim3(CCH, 2), 128>>>(in1, in2);
    sum_kernel<<<dim3(NPART, 2, CCH), 256>>>(in1, in2);
    coef_kernel<<<CCH, 256>>>(W, b);
    combine_kernel<<<CCH * (NQ / 256), 256>>>((const float4*)in1,
                                              (const float4*)in2,
                                              (float4*)out);
}